// round 1
// baseline (speedup 1.0000x reference)
#include <cuda_runtime.h>

#define OUT_DIM 4096
#define IN_DIM  8192
#define ALPHA   0.001f
#define EPS     1e-12f

// Scratch (no allocs allowed)
__device__ float g_y[OUT_DIM];   // raw projection
__device__ float g_yv[OUT_DIM];  // normalized projection

// ---------------------------------------------------------------------------
// Kernel 1: GEMV  y[r] = dot(W[r,:], x)   (one block per row, float4 loads)
// ---------------------------------------------------------------------------
__global__ void __launch_bounds__(256) gemv_kernel(
    const float* __restrict__ W, const float* __restrict__ x, float* __restrict__ y)
{
    const int row  = blockIdx.x;
    const int tid  = threadIdx.x;
    const float4* Wr = reinterpret_cast<const float4*>(W + (size_t)row * IN_DIM);
    const float4* x4 = reinterpret_cast<const float4*>(x);

    float s = 0.0f;
#pragma unroll
    for (int i = tid; i < IN_DIM / 4; i += 256) {
        float4 w = Wr[i];
        float4 v = x4[i];
        s += w.x * v.x + w.y * v.y + w.z * v.z + w.w * v.w;
    }
    // warp reduce
#pragma unroll
    for (int o = 16; o > 0; o >>= 1) s += __shfl_down_sync(0xFFFFFFFFu, s, o);

    __shared__ float red[8];
    if ((tid & 31) == 0) red[tid >> 5] = s;
    __syncthreads();
    if (tid < 8) {
        s = red[tid];
#pragma unroll
        for (int o = 4; o > 0; o >>= 1) s += __shfl_down_sync(0xFFu, s, o);
        if (tid == 0) y[row] = s;
    }
}

// ---------------------------------------------------------------------------
// Kernel 2: L2-normalize y -> yv, write y_n to output head. Single block.
// ---------------------------------------------------------------------------
__global__ void __launch_bounds__(1024) normalize_kernel(
    const float* __restrict__ y, float* __restrict__ yv, float* __restrict__ out_yn)
{
    const int tid = threadIdx.x;
    float ss = 0.0f;
#pragma unroll
    for (int i = tid; i < OUT_DIM; i += 1024) {
        float v = y[i];
        ss += v * v;
    }
#pragma unroll
    for (int o = 16; o > 0; o >>= 1) ss += __shfl_down_sync(0xFFFFFFFFu, ss, o);

    __shared__ float red[32];
    if ((tid & 31) == 0) red[tid >> 5] = ss;
    __syncthreads();
    __shared__ float s_inv;
    if (tid < 32) {
        float t = red[tid];
#pragma unroll
        for (int o = 16; o > 0; o >>= 1) t += __shfl_down_sync(0xFFFFFFFFu, t, o);
        if (tid == 0) {
            float nrm = sqrtf(t);
            nrm = fmaxf(nrm, EPS);
            s_inv = 1.0f / nrm;
        }
    }
    __syncthreads();
    const float inv = s_inv;
#pragma unroll
    for (int i = tid; i < OUT_DIM; i += 1024) {
        float v = y[i] * inv;
        yv[i]     = v;
        out_yn[i] = v;
    }
}

// ---------------------------------------------------------------------------
// Kernel 3: column-wise inclusive scan of W*yv + Sanger update.
// Block: 256 threads = 8 warps. lane -> column (32 cols/block, coalesced),
// warp  -> segment of 512 rows.
// Phase 1: per-segment partial sums.  Phase 2 (REVERSE row order, maximizes
// L2 hits on the re-read): apply update while reconstructing the running sum.
// ---------------------------------------------------------------------------
#define SEG_ROWS 512
#define NSEG     8

__global__ void __launch_bounds__(256) sanger_kernel(
    const float* __restrict__ W, const float* __restrict__ x,
    const float* __restrict__ yv, float* __restrict__ Wout)
{
    __shared__ float s_yv[OUT_DIM];
    __shared__ float s_part[NSEG][33];

    const int tid  = threadIdx.x;
    const int lane = tid & 31;
    const int seg  = tid >> 5;
    const int col  = blockIdx.x * 32 + lane;

    // stage yv in shared
#pragma unroll
    for (int i = tid; i < OUT_DIM; i += 256) s_yv[i] = yv[i];
    __syncthreads();

    const float xc = x[col];
    const int row0 = seg * SEG_ROWS;

    // Phase 1: segment partial sum of W[j][col] * yv[j]
    float p = 0.0f;
    {
        const float* Wp = W + (size_t)row0 * IN_DIM + col;
#pragma unroll 8
        for (int j = 0; j < SEG_ROWS; ++j) {
            p += Wp[(size_t)j * IN_DIM] * s_yv[row0 + j];
        }
    }
    s_part[seg][lane] = p;
    __syncthreads();

    // exclusive prefix over segments for this column
    float excl = 0.0f;
#pragma unroll
    for (int t = 0; t < NSEG; ++t)
        if (t < seg) excl += s_part[t][lane];

    // Phase 2: reverse order. s_run starts as inclusive sum through the
    // segment's last row; after emitting row j, subtract its contribution.
    float s_run = excl + p;
    {
        const float* Wp = W    + (size_t)row0 * IN_DIM + col;
        float*       Op = Wout + (size_t)row0 * IN_DIM + col;
#pragma unroll 8
        for (int j = SEG_ROWS - 1; j >= 0; --j) {
            float w  = Wp[(size_t)j * IN_DIM];
            float yj = s_yv[row0 + j];
            Op[(size_t)j * IN_DIM] = w + ALPHA * yj * (xc - s_run);
            s_run -= w * yj;
        }
    }
}

// ---------------------------------------------------------------------------
extern "C" void kernel_launch(void* const* d_in, const int* in_sizes, int n_in,
                              void* d_out, int out_size)
{
    const float* x = (const float*)d_in[0];  // [1, 8192]
    const float* W = (const float*)d_in[1];  // [4096, 8192]
    float* out = (float*)d_out;              // [4096 y_n] ++ [4096*8192 W_new]

    float* y  = nullptr;
    float* yv = nullptr;
    cudaGetSymbolAddress((void**)&y,  g_y);
    cudaGetSymbolAddress((void**)&yv, g_yv);

    gemv_kernel<<<OUT_DIM, 256>>>(W, x, y);
    normalize_kernel<<<1, 1024>>>(y, yv, out);
    sanger_kernel<<<IN_DIM / 32, 256>>>(W, x, yv, out + OUT_DIM);
}